// round 5
// baseline (speedup 1.0000x reference)
#include <cuda_runtime.h>

// Problem constants
#define NROWS     524288
#define NCH       30
#define TILE_ROWS 32
#define THREADS   256
#define WARPS_BLK 8
#define NTILES    (NROWS / TILE_ROWS)          // 16384
#define NBLOCKS   (NTILES / WARPS_BLK)         // 2048

// FILTERS (6 x 30), compile-time constant from the reference
__constant__ float c_FILT[6 * 30] = {
    1,1,1,1,1,1,1,1,1,1,1,1,1,1,1,1,1,1,1,1,1,1,0,0,0,0,0,0,1,1,
    1,1,0,0,0,0,0,0,0,0,0,0,0,0,0,0,1,1,1,1,1,1,0,0,1,1,1,1,1,1,
    1,1,0,0,1,1,0,0,1,1,0,0,1,1,0,0,0,0,0,0,0,0,0,0,0,0,0,0,1,1,
    1,1,0,0,0,0,0,0,0,0,0,0,0,0,1,1,1,1,1,1,1,1,0,0,0,0,1,1,1,1,
    1,1,0,0,1,0,0,0,0,0,0,0,0,0,0,0,0,0,0,0,0,0,0,0,0,0,0,0,1,1,
    1,1,1,1,0,0,1,1,0,0,1,1,0,0,0,0,0,0,0,0,0,0,0,0,0,0,0,0,1,1
};

__global__ __launch_bounds__(THREADS)
void ext_kernel(const float* __restrict__ tpl,   // (N,3)
                const float* __restrict__ cons,  // (N,8)
                const float* __restrict__ w_gas, // (8,30)
                const float* __restrict__ W1,    // (6,6,2)
                const float* __restrict__ b1,    // (6,6)
                const float* __restrict__ W2,    // (6,4,6)
                const float* __restrict__ b2,    // (6,4)
                const float* __restrict__ W3,    // (6,4,4)
                const float* __restrict__ b3,    // (6,4)
                const float* __restrict__ Wo,    // (6,4)
                const float* __restrict__ bo,    // (6,)
                float* __restrict__ out)         // (N,30,8)
{
    __shared__ float sW1[72], sb1[36], sW2[144], sb2[24];
    __shared__ float sW3[96], sb3[24], sWo[24], sbo[6];
    __shared__ __align__(16) float sTAB[240];                       // TAB[ch*8 + j]
    __shared__ __align__(16) float sV[WARPS_BLK][TILE_ROWS * 8];    // warp-private v

    const int tid  = threadIdx.x;
    const int wid  = tid >> 5;
    const int lane = tid & 31;

    // ---- stage weights + build TAB = exp(w_gas[j,ch]) * (j<2 ? 1 : FILT[j-2,ch]) ----
    if (tid < 144) sW2[tid] = W2[tid];
    if (tid < 96)  sW3[tid] = W3[tid];
    if (tid < 72)  sW1[tid] = W1[tid];
    if (tid < 36)  sb1[tid] = b1[tid];
    if (tid < 24)  { sb2[tid] = b2[tid]; sb3[tid] = b3[tid]; sWo[tid] = Wo[tid]; }
    if (tid < 6)   sbo[tid] = bo[tid];
    if (tid < 240) {
        int ch = tid >> 3, j = tid & 7;
        float e = __expf(w_gas[j * NCH + ch]);
        if (j >= 2) e *= c_FILT[(j - 2) * NCH + ch];
        sTAB[tid] = e;
    }
    __syncthreads();   // the ONLY block-wide barrier

    const int tile = blockIdx.x * WARPS_BLK + wid;   // one 32-row tile per warp
    const int n    = tile * TILE_ROWS + lane;

    // ---- per-lane MLP for its own row -> v[8] ----
    {
        const float t0 = tpl[n * 3 + 0];
        const float t1 = tpl[n * 3 + 1];
        const float4 c0 = reinterpret_cast<const float4*>(cons)[n * 2 + 0];
        const float4 c1 = reinterpret_cast<const float4*>(cons)[n * 2 + 1];

        float s[6];
        #pragma unroll
        for (int g = 0; g < 6; g++) {
            float h1[6];
            #pragma unroll
            for (int h = 0; h < 6; h++) {
                float a = fmaf(sW1[g*12 + h*2 + 0], t0,
                          fmaf(sW1[g*12 + h*2 + 1], t1, sb1[g*6 + h]));
                h1[h] = fmaxf(a, 0.0f);
            }
            float h2[4];
            #pragma unroll
            for (int o = 0; o < 4; o++) {
                float a = sb2[g*4 + o];
                #pragma unroll
                for (int h = 0; h < 6; h++) a = fmaf(sW2[g*24 + o*6 + h], h1[h], a);
                h2[o] = fmaxf(a, 0.0f);
            }
            float h3[4];
            #pragma unroll
            for (int p = 0; p < 4; p++) {
                float a = sb3[g*4 + p];
                #pragma unroll
                for (int h = 0; h < 4; h++) a = fmaf(sW3[g*16 + p*4 + h], h2[h], a);
                h3[p] = fmaxf(a, 0.0f);
            }
            float z = sbo[g];
            #pragma unroll
            for (int p = 0; p < 4; p++) z = fmaf(sWo[g*4 + p], h3[p], z);
            s[g] = __fdividef(1.0f, 1.0f + __expf(-z));   // sigmoid
        }

        float4 v0 = make_float4(c0.x,         c0.y,         c0.z * s[0], c0.w * s[1]);
        float4 v1 = make_float4(c1.x * s[2],  c1.y * s[3],  c1.z * s[4], c1.w * s[5]);
        float4* vb = reinterpret_cast<float4*>(sV[wid]);
        vb[lane * 2 + 0] = v0;
        vb[lane * 2 + 1] = v1;
    }
    __syncwarp();

    // ---- warp streams its tile: 32 rows x 60 float4 = 60 coalesced 512B stores ----
    {
        const float4* vb  = reinterpret_cast<const float4*>(sV[wid]);
        const float4* tb  = reinterpret_cast<const float4*>(sTAB);
        float4* op = reinterpret_cast<float4*>(out) + (size_t)tile * (TILE_ROWS * 60) + lane;

        #pragma unroll 4
        for (int it = 0; it < 60; it++) {
            const int idx = it * 32 + lane;        // 0..1919
            const int row = idx / 60;
            const int rem = idx - row * 60;
            float4 tab = tb[rem];
            float4 vv  = vb[row * 2 + (rem & 1)];
            float4 r;
            r.x = vv.x * tab.x;
            r.y = vv.y * tab.y;
            r.z = vv.z * tab.z;
            r.w = vv.w * tab.w;
            op[it * 32] = r;
        }
    }
}

extern "C" void kernel_launch(void* const* d_in, const int* in_sizes, int n_in,
                              void* d_out, int out_size) {
    (void)in_sizes; (void)n_in; (void)out_size;
    ext_kernel<<<NBLOCKS, THREADS>>>(
        (const float*)d_in[0],  // tpl
        (const float*)d_in[1],  // cons
        (const float*)d_in[2],  // w_gas
        (const float*)d_in[3],  // ke_W1
        (const float*)d_in[4],  // ke_b1
        (const float*)d_in[5],  // ke_W2
        (const float*)d_in[6],  // ke_b2
        (const float*)d_in[7],  // ke_W3
        (const float*)d_in[8],  // ke_b3
        (const float*)d_in[9],  // ke_Wo
        (const float*)d_in[10], // ke_bo
        (float*)d_out);
}

// round 6
// speedup vs baseline: 1.0007x; 1.0007x over previous
#include <cuda_runtime.h>
#include <cstdint>

// Problem constants
#define NROWS      524288
#define NCH        30
#define TILE_ROWS  32                      // rows per warp
#define WARPS_BLK  4
#define THREADS    (WARPS_BLK * 32)        // 128
#define NTILES     (NROWS / TILE_ROWS)     // 16384
#define NBLOCKS    (NTILES / WARPS_BLK)    // 4096
#define CHUNK_ROWS 4
#define CHUNK_F4   (CHUNK_ROWS * 60)       // 240 float4 = 3840 B
#define NCHUNKS    (TILE_ROWS / CHUNK_ROWS) // 8
#define NBUF       2

// FILTERS (6 x 30), compile-time constant from the reference
__constant__ float c_FILT[6 * 30] = {
    1,1,1,1,1,1,1,1,1,1,1,1,1,1,1,1,1,1,1,1,1,1,0,0,0,0,0,0,1,1,
    1,1,0,0,0,0,0,0,0,0,0,0,0,0,0,0,1,1,1,1,1,1,0,0,1,1,1,1,1,1,
    1,1,0,0,1,1,0,0,1,1,0,0,1,1,0,0,0,0,0,0,0,0,0,0,0,0,0,0,1,1,
    1,1,0,0,0,0,0,0,0,0,0,0,0,0,1,1,1,1,1,1,1,1,0,0,0,0,1,1,1,1,
    1,1,0,0,1,0,0,0,0,0,0,0,0,0,0,0,0,0,0,0,0,0,0,0,0,0,0,0,1,1,
    1,1,1,1,0,0,1,1,0,0,1,1,0,0,0,0,0,0,0,0,0,0,0,0,0,0,0,0,1,1
};

__device__ __forceinline__ void bulk_store(void* gptr, uint32_t smem_addr, uint32_t bytes) {
    asm volatile(
        "cp.async.bulk.global.shared::cta.bulk_group [%0], [%1], %2;"
        :: "l"(gptr), "r"(smem_addr), "r"(bytes) : "memory");
}

__global__ __launch_bounds__(THREADS)
void ext_kernel(const float* __restrict__ tpl,   // (N,3)
                const float* __restrict__ cons,  // (N,8)
                const float* __restrict__ w_gas, // (8,30)
                const float* __restrict__ W1,    // (6,6,2)
                const float* __restrict__ b1,    // (6,6)
                const float* __restrict__ W2,    // (6,4,6)
                const float* __restrict__ b2,    // (6,4)
                const float* __restrict__ W3,    // (6,4,4)
                const float* __restrict__ b3,    // (6,4)
                const float* __restrict__ Wo,    // (6,4)
                const float* __restrict__ bo,    // (6,)
                float* __restrict__ out)         // (N,30,8)
{
    __shared__ float sW1[72], sb1[36], sW2[144], sb2[24];
    __shared__ float sW3[96], sb3[24], sWo[24], sbo[6];
    __shared__ __align__(16) float sTAB[240];                      // TAB[ch*8 + j]
    __shared__ __align__(16) float sV[WARPS_BLK][TILE_ROWS * 8];   // per-warp v[row][8]
    __shared__ __align__(16) float4 sStage[WARPS_BLK][NBUF][CHUNK_F4]; // 4*2*3840B

    const int tid  = threadIdx.x;
    const int wid  = tid >> 5;
    const int lane = tid & 31;

    // ---- stage weights + build TAB (128 threads -> strided loops) ----
    for (int i = tid; i < 144; i += THREADS) sW2[i] = W2[i];
    for (int i = tid; i < 96;  i += THREADS) sW3[i] = W3[i];
    if (tid < 72) sW1[tid] = W1[tid];
    if (tid < 36) sb1[tid] = b1[tid];
    if (tid < 24) { sb2[tid] = b2[tid]; sb3[tid] = b3[tid]; sWo[tid] = Wo[tid]; }
    if (tid < 6)  sbo[tid] = bo[tid];
    for (int i = tid; i < 240; i += THREADS) {
        int ch = i >> 3, j = i & 7;
        float e = __expf(w_gas[j * NCH + ch]);
        if (j >= 2) e *= c_FILT[(j - 2) * NCH + ch];
        sTAB[i] = e;
    }
    __syncthreads();   // only block-wide barrier

    const int tile = blockIdx.x * WARPS_BLK + wid;   // one 32-row tile per warp
    const int n    = tile * TILE_ROWS + lane;

    // ---- per-lane MLP for its own row -> v[8] into warp-private sV ----
    {
        const float t0 = tpl[n * 3 + 0];
        const float t1 = tpl[n * 3 + 1];
        const float4 c0 = reinterpret_cast<const float4*>(cons)[n * 2 + 0];
        const float4 c1 = reinterpret_cast<const float4*>(cons)[n * 2 + 1];

        float s[6];
        #pragma unroll
        for (int g = 0; g < 6; g++) {
            float h1[6];
            #pragma unroll
            for (int h = 0; h < 6; h++) {
                float a = fmaf(sW1[g*12 + h*2 + 0], t0,
                          fmaf(sW1[g*12 + h*2 + 1], t1, sb1[g*6 + h]));
                h1[h] = fmaxf(a, 0.0f);
            }
            float h2[4];
            #pragma unroll
            for (int o = 0; o < 4; o++) {
                float a = sb2[g*4 + o];
                #pragma unroll
                for (int h = 0; h < 6; h++) a = fmaf(sW2[g*24 + o*6 + h], h1[h], a);
                h2[o] = fmaxf(a, 0.0f);
            }
            float h3[4];
            #pragma unroll
            for (int p = 0; p < 4; p++) {
                float a = sb3[g*4 + p];
                #pragma unroll
                for (int h = 0; h < 4; h++) a = fmaf(sW3[g*16 + p*4 + h], h2[h], a);
                h3[p] = fmaxf(a, 0.0f);
            }
            float z = sbo[g];
            #pragma unroll
            for (int p = 0; p < 4; p++) z = fmaf(sWo[g*4 + p], h3[p], z);
            s[g] = __fdividef(1.0f, 1.0f + __expf(-z));   // sigmoid
        }

        float4* vb = reinterpret_cast<float4*>(sV[wid]);
        vb[lane * 2 + 0] = make_float4(c0.x,        c0.y,        c0.z * s[0], c0.w * s[1]);
        vb[lane * 2 + 1] = make_float4(c1.x * s[2], c1.y * s[3], c1.z * s[4], c1.w * s[5]);
    }
    __syncwarp();

    // ---- warp-private TMA pipeline: 8 chunks x 3840B, double buffered ----
    const float4* vb = reinterpret_cast<const float4*>(sV[wid]);
    const float4* tb = reinterpret_cast<const float4*>(sTAB);
    char* gbase = reinterpret_cast<char*>(out) + (size_t)tile * (TILE_ROWS * 960);

    #pragma unroll 2
    for (int k = 0; k < NCHUNKS; k++) {
        const int buf = k & 1;
        if (k >= NBUF) {
            if (lane == 0)
                asm volatile("cp.async.bulk.wait_group.read %0;" :: "n"(NBUF - 1) : "memory");
            __syncwarp();
        }
        // stage chunk k (rows k*4 .. k*4+3): 240 float4, 32 lanes
        float4* st = sStage[wid][buf];
        #pragma unroll
        for (int c = 0; c < 8; c++) {
            const int idx = c * 32 + lane;
            if (c < 7 || lane < 16) {          // idx < 240
                const int row = idx / 60;
                const int rem = idx - row * 60;
                float4 tab = tb[rem];
                float4 vv  = vb[(k * CHUNK_ROWS + row) * 2 + (rem & 1)];
                float4 r;
                r.x = vv.x * tab.x;
                r.y = vv.y * tab.y;
                r.z = vv.z * tab.z;
                r.w = vv.w * tab.w;
                st[idx] = r;
            }
        }
        asm volatile("fence.proxy.async.shared::cta;" ::: "memory");
        __syncwarp();
        if (lane == 0) {
            uint32_t saddr = (uint32_t)__cvta_generic_to_shared(st);
            bulk_store(gbase + (size_t)k * (CHUNK_ROWS * 960), saddr, CHUNK_ROWS * 960);
            asm volatile("cp.async.bulk.commit_group;" ::: "memory");
        }
    }
    if (lane == 0)
        asm volatile("cp.async.bulk.wait_group 0;" ::: "memory");
}

extern "C" void kernel_launch(void* const* d_in, const int* in_sizes, int n_in,
                              void* d_out, int out_size) {
    (void)in_sizes; (void)n_in; (void)out_size;
    ext_kernel<<<NBLOCKS, THREADS>>>(
        (const float*)d_in[0],  // tpl
        (const float*)d_in[1],  // cons
        (const float*)d_in[2],  // w_gas
        (const float*)d_in[3],  // ke_W1
        (const float*)d_in[4],  // ke_b1
        (const float*)d_in[5],  // ke_W2
        (const float*)d_in[6],  // ke_b2
        (const float*)d_in[7],  // ke_W3
        (const float*)d_in[8],  // ke_b3
        (const float*)d_in[9],  // ke_Wo
        (const float*)d_in[10], // ke_bo
        (float*)d_out);
}